// round 2
// baseline (speedup 1.0000x reference)
#include <cuda_runtime.h>

#define BB 256
#define D_IN 2048
#define HID 2048
#define NSEG 10
#define D_CTX 1024
#define OUT_DIM 100
#define KWIN 102
#define SEG_STRIDE 192
#define FF_STRIDE 256
#define NROWS_SEG (HID*NSEG)

struct __align__(8) Ent { float v; unsigned off; };

// ---- static scratch (no allocation allowed) ----
__device__ Ent   g_segL[2][NROWS_SEG*SEG_STRIDE];   // ~63 MB
__device__ int   g_segCnt[2][NROWS_SEG];
__device__ Ent   g_ffL[2][HID*FF_STRIDE];           // ~8.4 MB
__device__ int   g_ffCnt[2][HID];
__device__ float g_ctxT[D_CTX*BB];                  // [c][b]
__device__ float g_xT[D_IN*BB];                     // [j][b]
__device__ float g_hT[HID*BB];                      // [u][b]
__device__ float g_yffT[HID*BB];
__device__ float g_yT[HID*BB];
__device__ Ent   g_win[BB*KWIN];

// ---------------- transpose: in [R=256][C] -> global [C][256] ----------------
__global__ void transpose_kernel(const float* __restrict__ in, int C, int which)
{
    __shared__ float t[32][33];
    float* out = which ? g_xT : g_ctxT;
    int c0 = blockIdx.x*32, r0 = blockIdx.y*32;
    int x = threadIdx.x, y0 = threadIdx.y;
    for (int yy = y0; yy < 32; yy += 8)
        t[yy][x] = in[(size_t)(r0+yy)*C + c0 + x];
    __syncthreads();
    for (int yy = y0; yy < 32; yy += 8)
        out[(size_t)(c0+yy)*BB + r0 + x] = t[x][yy];
}

// ---------------- deterministic order-preserving sparse extraction ----------------
// 128 threads/block, thread t owns contiguous chunk of Q float4s.
template<int COLS, int STRIDE, int OFFSHIFT, bool SEG>
__global__ void extract_kernel(const float* __restrict__ w, const float* __restrict__ m, int layer)
{
    constexpr int Q = COLS/4/128;           // float4 per thread (2 for seg, 4 for ff)
    int row = blockIdx.x, tid = threadIdx.x;
    const float4* w4 = (const float4*)(w + (size_t)row*COLS) + tid*Q;
    const float4* m4 = (const float4*)(m + (size_t)row*COLS) + tid*Q;
    float pv[4*Q];
#pragma unroll
    for (int i = 0; i < Q; i++) {
        float4 a = w4[i], b = m4[i];
        pv[4*i+0] = a.x*b.x; pv[4*i+1] = a.y*b.y;
        pv[4*i+2] = a.z*b.z; pv[4*i+3] = a.w*b.w;
    }
    int myCount = 0;
#pragma unroll
    for (int j = 0; j < 4*Q; j++) myCount += (pv[j] != 0.f);

    // block exclusive scan of counts (index-order preserving)
    int lane = tid & 31, wrp = tid >> 5;
    int inc = myCount;
#pragma unroll
    for (int d = 1; d < 32; d <<= 1) {
        int nv = __shfl_up_sync(0xFFFFFFFFu, inc, d);
        if (lane >= d) inc += nv;
    }
    __shared__ int wsum[4];
    if (lane == 31) wsum[wrp] = inc;
    __syncthreads();
    int base = inc - myCount;
    for (int i = 0; i < wrp; i++) base += wsum[i];

    Ent* out = (SEG ? g_segL[layer] : g_ffL[layer]) + (size_t)row*STRIDE;
    int pos = base;
#pragma unroll
    for (int j = 0; j < 4*Q; j++) {
        if (pv[j] != 0.f) {
            if (pos < STRIDE) {
                out[pos].v = pv[j];
                out[pos].off = (unsigned)((tid*4*Q + j) << OFFSHIFT);
            }
            pos++;
        }
    }
    if (tid == 0) {
        int tot = wsum[0]+wsum[1]+wsum[2]+wsum[3];
        int* cnt = SEG ? g_segCnt[layer] : g_ffCnt[layer];
        cnt[row] = tot < STRIDE ? tot : STRIDE;
    }
}

// ---------------- sparse feedforward: yffT[u][b] = sum_nz inT[j][b]*w + bias ----------------
// block 512 thr (16 warps), 4 u per warp, b-tile 32 in smem, two j-phases of 1024
__global__ void __launch_bounds__(512,1) ff_kernel(int layer, const float* __restrict__ bias)
{
    extern __shared__ float sx[];   // [1024][32]
    const float* inT = layer ? g_hT : g_xT;
    const Ent* lists = g_ffL[layer];
    const int* cnts  = g_ffCnt[layer];
    int tid = threadIdx.x, lane = tid & 31, wid = tid >> 5;
    int b0 = blockIdx.y*32, u0 = blockIdx.x*64;
    float acc[4] = {0.f,0.f,0.f,0.f};
    for (int ph = 0; ph < 2; ph++) {
        __syncthreads();
        for (int jj = wid; jj < 1024; jj += 16)
            sx[jj*32 + lane] = inT[(size_t)((ph<<10)+jj)*BB + b0 + lane];
        __syncthreads();
        unsigned lo = (unsigned)(ph << 10);
#pragma unroll
        for (int k = 0; k < 4; k++) {
            int u = u0 + wid + k*16;
            int n = cnts[u];
            const Ent* p = lists + (size_t)u*FF_STRIDE;
            float a0 = 0.f, a1 = 0.f;
            int i = 0;
            for (; i + 4 <= n; i += 4) {
                Ent e0 = p[i], e1 = p[i+1], e2 = p[i+2], e3 = p[i+3];
                unsigned c0 = e0.off - lo, c1 = e1.off - lo, c2 = e2.off - lo, c3 = e3.off - lo;
                if (c0 < 1024u) a0 += sx[c0*32 + lane]*e0.v;
                if (c1 < 1024u) a1 += sx[c1*32 + lane]*e1.v;
                if (c2 < 1024u) a0 += sx[c2*32 + lane]*e2.v;
                if (c3 < 1024u) a1 += sx[c3*32 + lane]*e3.v;
            }
            for (; i < n; i++) {
                unsigned c0 = p[i].off - lo;
                if (c0 < 1024u) a0 += sx[c0*32 + lane]*p[i].v;
            }
            acc[k] += a0 + a1;
        }
    }
#pragma unroll
    for (int k = 0; k < 4; k++) {
        int u = u0 + wid + k*16;
        g_yffT[(size_t)u*BB + b0 + lane] = acc[k] + bias[u];
    }
}

// ---------------- sparse dendrite einsum + abs-argmax gate ----------------
// block 512 thr, 4 u per warp (sequential), b-tile 32, ctx tile fully in smem
__global__ void __launch_bounds__(512,1) dend_kernel(int layer)
{
    extern __shared__ float sc[];   // [1024][32]
    const Ent* lists = g_segL[layer];
    const int* cnts  = g_segCnt[layer];
    int tid = threadIdx.x, lane = tid & 31, wid = tid >> 5;
    int b0 = blockIdx.y*32, u0 = blockIdx.x*64;
    for (int jj = wid; jj < 1024; jj += 16)
        sc[jj*32 + lane] = g_ctxT[(size_t)jj*BB + b0 + lane];
    __syncthreads();
    const char* cbase = (const char*)sc + lane*4;
#pragma unroll 1
    for (int k = 0; k < 4; k++) {
        int u = u0 + wid + k*16;
        float best = -1.f, chosen = 0.f;
        const Ent* ub = lists + (size_t)(u*NSEG)*SEG_STRIDE;
#pragma unroll 1
        for (int s = 0; s < NSEG; s++) {
            int n = cnts[u*NSEG + s];
            const Ent* p = ub + (size_t)s*SEG_STRIDE;
            float a0 = 0.f, a1 = 0.f;
            int i = 0;
            for (; i + 4 <= n; i += 4) {
                Ent e0 = p[i], e1 = p[i+1], e2 = p[i+2], e3 = p[i+3];
                a0 += *(const float*)(cbase + e0.off) * e0.v;
                a1 += *(const float*)(cbase + e1.off) * e1.v;
                a0 += *(const float*)(cbase + e2.off) * e2.v;
                a1 += *(const float*)(cbase + e3.off) * e3.v;
            }
            for (; i < n; i++)
                a0 += *(const float*)(cbase + p[i].off) * p[i].v;
            float d = a0 + a1;
            float ad = fabsf(d);
            if (ad > best) { best = ad; chosen = d; }   // strict > keeps first index (argmax tie rule)
        }
        float gate = 1.f / (1.f + __expf(-chosen));
        size_t o = (size_t)u*BB + b0 + lane;
        g_yT[o] = g_yffT[o] * gate;
    }
}

// ---------------- exact per-row top-K (radix select on order-preserved keys) ----------------
__global__ void kwin_kernel()
{
    __shared__ unsigned keys[HID];
    __shared__ float vals[HID];
    __shared__ int hist[256];
    __shared__ int s_digit, s_kk;
    __shared__ unsigned char keep[HID];
    int b = blockIdx.x, tid = threadIdx.x;   // 256 threads
    for (int r = 0; r < HID/256; r++) {
        int u = tid + r*256;
        float f = g_yT[(size_t)u*BB + b];
        vals[u] = f;
        unsigned x = __float_as_uint(f);
        keys[u] = (x & 0x80000000u) ? ~x : (x | 0x80000000u);
    }
    if (tid == 0) s_kk = KWIN;
    __syncthreads();
    unsigned pref = 0, pmask = 0;
    for (int pass = 0; pass < 4; pass++) {
        int shift = 24 - 8*pass;
        hist[tid] = 0;
        __syncthreads();
        for (int r = 0; r < HID/256; r++) {
            unsigned kk = keys[tid + r*256];
            if ((kk & pmask) == pref) atomicAdd(&hist[(kk >> shift) & 255], 1);
        }
        __syncthreads();
        if (tid == 0) {
            int kk = s_kk, d = 255;
            for (; d > 0; d--) { if (hist[d] >= kk) break; kk -= hist[d]; }
            s_digit = d; s_kk = kk;
        }
        __syncthreads();
        pref  |= ((unsigned)s_digit) << shift;
        pmask |= 0xFFu << shift;
    }
    unsigned kth = pref;
    int need_eq = s_kk;   // keep this many of the ==kth elements, smallest index first
    for (int r = 0; r < HID/256; r++) {
        int u = tid + r*256;
        unsigned kk = keys[u];
        bool kp = (kk > kth);
        if (kk == kth) {
            int cnt = 0;
            for (int j = 0; j < u; j++) if (keys[j] == kth) cnt++;
            kp = (cnt < need_eq);
        }
        keep[u] = kp;
        g_hT[(size_t)u*BB + b] = kp ? vals[u] : 0.f;
    }
    __syncthreads();
    if (tid < 32) {   // deterministic index-ordered winner list
        int base = 0;
        for (int ch = 0; ch < HID/32; ch++) {
            int u = ch*32 + tid;
            bool kp = keep[u] != 0;
            unsigned mm = __ballot_sync(0xFFFFFFFFu, kp);
            if (kp) {
                int pos = base + __popc(mm & ((1u << tid) - 1u));
                g_win[b*KWIN + pos].v = vals[u];
                g_win[b*KWIN + pos].off = (unsigned)u;
            }
            base += __popc(mm);
        }
    }
}

// ---------------- Dale (EiDense) output head on winner lists ----------------
__global__ void out_kernel(const float* __restrict__ Wex, const float* __restrict__ Wix,
                           const float* __restrict__ Wei, const float* __restrict__ bout,
                           float* __restrict__ out)
{
    __shared__ float sv[KWIN];
    __shared__ int   si[KWIN];
    __shared__ float red[128];
    int b = blockIdx.x, tid = threadIdx.x;   // 128 threads
    if (tid < KWIN) { Ent e = g_win[b*KWIN + tid]; sv[tid] = e.v; si[tid] = (int)e.off; }
    __syncthreads();
    float tpart = 0.f;
    for (int k = tid; k < KWIN; k += 128) tpart += sv[k]*Wix[si[k]];
    red[tid] = tpart;
    __syncthreads();
    for (int s = 64; s > 0; s >>= 1) { if (tid < s) red[tid] += red[tid+s]; __syncthreads(); }
    float t = red[0];
    if (tid < OUT_DIM) {
        float a = 0.f;
        const float* Wr = Wex + (size_t)tid*HID;
        for (int k = 0; k < KWIN; k++) a += sv[k]*Wr[si[k]];
        out[b*OUT_DIM + tid] = a - Wei[tid]*t + bout[tid];
    }
}

// ---------------- launch ----------------
extern "C" void kernel_launch(void* const* d_in, const int* in_sizes, int n_in,
                              void* d_out, int out_size)
{
    const float* x      = (const float*)d_in[0];
    const float* ctx    = (const float*)d_in[1];
    const float* W1     = (const float*)d_in[2];
    const float* b1     = (const float*)d_in[3];
    const float* segW1  = (const float*)d_in[4];
    const float* maskW1 = (const float*)d_in[5];
    const float* maskS1 = (const float*)d_in[6];
    const float* W2     = (const float*)d_in[7];
    const float* b2     = (const float*)d_in[8];
    const float* segW2  = (const float*)d_in[9];
    const float* maskW2 = (const float*)d_in[10];
    const float* maskS2 = (const float*)d_in[11];
    const float* Wex    = (const float*)d_in[12];
    const float* Wix    = (const float*)d_in[13];
    const float* Wei    = (const float*)d_in[14];
    const float* bout   = (const float*)d_in[15];
    float* out = (float*)d_out;

    cudaFuncSetAttribute((const void*)ff_kernel,   cudaFuncAttributeMaxDynamicSharedMemorySize, 131072);
    cudaFuncSetAttribute((const void*)dend_kernel, cudaFuncAttributeMaxDynamicSharedMemorySize, 131072);

    dim3 tb(32, 8);
    transpose_kernel<<<dim3(D_CTX/32, BB/32), tb>>>(ctx, D_CTX, 0);
    transpose_kernel<<<dim3(D_IN/32,  BB/32), tb>>>(x,   D_IN,  1);

    extract_kernel<D_CTX, SEG_STRIDE, 7, true ><<<NROWS_SEG, 128>>>(segW1, maskS1, 0);
    extract_kernel<D_CTX, SEG_STRIDE, 7, true ><<<NROWS_SEG, 128>>>(segW2, maskS2, 1);
    extract_kernel<D_IN,  FF_STRIDE,  0, false><<<HID,       128>>>(W1, maskW1, 0);
    extract_kernel<HID,   FF_STRIDE,  0, false><<<HID,       128>>>(W2, maskW2, 1);

    dim3 big(HID/64, BB/32);
    ff_kernel  <<<big, 512, 131072>>>(0, b1);
    dend_kernel<<<big, 512, 131072>>>(0);
    kwin_kernel<<<BB, 256>>>();

    ff_kernel  <<<big, 512, 131072>>>(1, b2);
    dend_kernel<<<big, 512, 131072>>>(1);
    kwin_kernel<<<BB, 256>>>();

    out_kernel<<<BB, 128>>>(Wex, Wix, Wei, bout, out);
}

// round 6
// speedup vs baseline: 1.6023x; 1.6023x over previous
#include <cuda_runtime.h>

#define BB 256
#define D_IN 2048
#define HID 2048
#define NSEG 10
#define D_CTX 1024
#define OUT_DIM 100
#define KWIN 102
#define NROWS_SEG (HID*NSEG)

// seg lists: 4 buckets of 256 cols, cap 48 each (stride 192/row)
#define SCAP 48
#define SEG_STRIDE (4*SCAP)
// ff lists: 2 buckets of 1024 cols, cap 104 each (stride 208/row)
#define FCAP 104
#define FF_STRIDE (2*FCAP)

struct __align__(8) Ent { float v; unsigned off; };

// ---- static scratch ----
__device__ Ent   g_segL[2][(size_t)NROWS_SEG*SEG_STRIDE];   // ~63 MB
__device__ int   g_segCnt[2][NROWS_SEG*4];
__device__ Ent   g_ffL[2][HID*FF_STRIDE];                   // ~6.8 MB
__device__ int   g_ffCnt[2][HID*2];
__device__ float g_ctxT[D_CTX*BB];                          // [c][b]
__device__ float g_xT[D_IN*BB];                             // [j][b]
__device__ float g_hT[HID*BB];                              // [u][b]
__device__ float g_yffT[HID*BB];
__device__ float g_yT[HID*BB];
__device__ Ent   g_win[BB*KWIN];

// ---------------- transpose: in [R=256][C] -> global [C][256] ----------------
__global__ void transpose_kernel(const float* __restrict__ in, int C, int which)
{
    __shared__ float t[32][33];
    float* out = which ? g_xT : g_ctxT;
    int c0 = blockIdx.x*32, r0 = blockIdx.y*32;
    int x = threadIdx.x, y0 = threadIdx.y;
    for (int yy = y0; yy < 32; yy += 8)
        t[yy][x] = in[(size_t)(r0+yy)*C + c0 + x];
    __syncthreads();
    for (int yy = y0; yy < 32; yy += 8)
        out[(size_t)(c0+yy)*BB + r0 + x] = t[x][yy];
}

// ---------------- seg extraction: bucketed by 256-col phase ----------------
// 128 thr/row; warp w = bucket w (cols [256w,256w+256)); thread owns 8 cols.
__global__ void extract_seg_kernel(const float* __restrict__ w, const float* __restrict__ m, int layer)
{
    int row = blockIdx.x, tid = threadIdx.x;
    int lane = tid & 31, wrp = tid >> 5;
    const float4* w4 = (const float4*)(w + (size_t)row*D_CTX) + tid*2;
    const float4* m4 = (const float4*)(m + (size_t)row*D_CTX) + tid*2;
    float pv[8];
#pragma unroll
    for (int i = 0; i < 2; i++) {
        float4 a = w4[i], b = m4[i];
        pv[4*i+0] = a.x*b.x; pv[4*i+1] = a.y*b.y;
        pv[4*i+2] = a.z*b.z; pv[4*i+3] = a.w*b.w;
    }
    int cnt = 0;
#pragma unroll
    for (int j = 0; j < 8; j++) cnt += (pv[j] != 0.f);
    int inc = cnt;
#pragma unroll
    for (int d = 1; d < 32; d <<= 1) {
        int nv = __shfl_up_sync(0xFFFFFFFFu, inc, d);
        if (lane >= d) inc += nv;
    }
    int base = inc - cnt;
    Ent* out = g_segL[layer] + (size_t)row*SEG_STRIDE + wrp*SCAP;
    int pos = base;
#pragma unroll
    for (int j = 0; j < 8; j++) {
        if (pv[j] != 0.f) {
            if (pos < SCAP) {
                out[pos].v = pv[j];
                out[pos].off = (unsigned)((lane*8 + j) << 9);   // j_local * 512B (128-batch float row)
            }
            pos++;
        }
    }
    int tot = __shfl_sync(0xFFFFFFFFu, inc, 31);
    if (lane == 0) g_segCnt[layer][row*4 + wrp] = tot < SCAP ? tot : SCAP;
}

// ---------------- ff extraction: bucketed by 1024-col phase ----------------
// 256 thr/row; bucket = tid>>7; thread owns 8 cols.
__global__ void extract_ff_kernel(const float* __restrict__ w, const float* __restrict__ m, int layer)
{
    __shared__ int wsum[8];
    int row = blockIdx.x, tid = threadIdx.x;
    int lane = tid & 31, wrp = tid >> 5;      // 8 warps
    int bucket = tid >> 7;                    // warps 0-3 -> 0, 4-7 -> 1
    const float4* w4 = (const float4*)(w + (size_t)row*2048) + tid*2;
    const float4* m4 = (const float4*)(m + (size_t)row*2048) + tid*2;
    float pv[8];
#pragma unroll
    for (int i = 0; i < 2; i++) {
        float4 a = w4[i], b = m4[i];
        pv[4*i+0] = a.x*b.x; pv[4*i+1] = a.y*b.y;
        pv[4*i+2] = a.z*b.z; pv[4*i+3] = a.w*b.w;
    }
    int cnt = 0;
#pragma unroll
    for (int j = 0; j < 8; j++) cnt += (pv[j] != 0.f);
    int inc = cnt;
#pragma unroll
    for (int d = 1; d < 32; d <<= 1) {
        int nv = __shfl_up_sync(0xFFFFFFFFu, inc, d);
        if (lane >= d) inc += nv;
    }
    if (lane == 31) wsum[wrp] = inc;
    __syncthreads();
    int base = inc - cnt;
    for (int i = bucket*4; i < wrp; i++) base += wsum[i];
    Ent* out = g_ffL[layer] + (size_t)(row*2 + bucket)*FCAP;
    int pos = base;
    int jl0 = (tid & 127)*8;                  // col index local to bucket
#pragma unroll
    for (int j = 0; j < 8; j++) {
        if (pv[j] != 0.f) {
            if (pos < FCAP) {
                out[pos].v = pv[j];
                out[pos].off = (unsigned)((jl0 + j) << 7);   // j_local * 128B (32-batch float row)
            }
            pos++;
        }
    }
    if ((tid & 127) == 127) {
        int tot = wsum[bucket*4] + wsum[bucket*4+1] + wsum[bucket*4+2] + wsum[bucket*4+3];
        g_ffCnt[layer][row*2 + bucket] = tot < FCAP ? tot : FCAP;
    }
}

// ---------------- sparse feedforward (b-tile 32, 2 phases, staged lists) ----------------
__global__ void __launch_bounds__(512,1) ff_kernel(int layer, const float* __restrict__ bias)
{
    extern __shared__ float sx[];                       // [1024][32] = 128KB
    Ent* stg = (Ent*)((char*)sx + 1024*32*4);           // 16 warps x 104 Ents
    const float* inT = layer ? g_hT : g_xT;
    const Ent* lists = g_ffL[layer];
    const int* cnts  = g_ffCnt[layer];
    int tid = threadIdx.x, lane = tid & 31, wid = tid >> 5;
    int b0 = blockIdx.y*32, u0 = blockIdx.x*64;
    float acc[4] = {0.f,0.f,0.f,0.f};
    Ent* st = stg + wid*FCAP;
    for (int ph = 0; ph < 2; ph++) {
        __syncthreads();
        for (int jj = wid; jj < 1024; jj += 16)
            sx[jj*32 + lane] = inT[(size_t)((ph<<10)+jj)*BB + b0 + lane];
        __syncthreads();
        // preload k=0 bucket into regs
        int u = u0 + wid;
        int n = cnts[u*2 + ph];
        const Ent* lp = lists + (size_t)(u*2 + ph)*FCAP;
        Ent e0 = {0,0}, e1 = {0,0}, e2 = {0,0}, e3 = {0,0};
        if (lane      < n) e0 = lp[lane];
        if (lane + 32 < n) e1 = lp[lane+32];
        if (lane + 64 < n) e2 = lp[lane+64];
        if (lane <  8 && lane + 96 < n) e3 = lp[lane+96];
#pragma unroll
        for (int k = 0; k < 4; k++) {
            st[lane] = e0; st[lane+32] = e1; st[lane+64] = e2;
            if (lane < 8) st[lane+96] = e3;
            __syncwarp();
            int ncur = n;
            if (k < 3) {
                u = u0 + wid + (k+1)*16;
                n = cnts[u*2 + ph];
                lp = lists + (size_t)(u*2 + ph)*FCAP;
                e0 = {0,0}; e1 = {0,0}; e2 = {0,0}; e3 = {0,0};
                if (lane      < n) e0 = lp[lane];
                if (lane + 32 < n) e1 = lp[lane+32];
                if (lane + 64 < n) e2 = lp[lane+64];
                if (lane <  8 && lane + 96 < n) e3 = lp[lane+96];
            }
            float a = acc[k];
            for (int j = 0; j < ncur; j++) {
                Ent q = st[j];
                a += *(const float*)((const char*)sx + q.off + lane*4) * q.v;
            }
            acc[k] = a;
            __syncwarp();
        }
    }
#pragma unroll
    for (int k = 0; k < 4; k++) {
        int u = u0 + wid + k*16;
        g_yffT[(size_t)u*BB + b0 + lane] = acc[k] + bias[u];
    }
}

// ---------------- dendrite einsum + gate (b-tile 128 float4, 4 phases, staged) ----------------
__global__ void __launch_bounds__(512,1) dend_kernel(int layer)
{
    extern __shared__ float tile[];                     // [256][128] = 128KB
    Ent* stg = (Ent*)((char*)tile + 256*128*4);         // 16 warps x 48 Ents
    const int* cnts = g_segCnt[layer];
    int tid = threadIdx.x, lane = tid & 31, wid = tid >> 5;
    int u = blockIdx.x*16 + wid;
    int b0 = blockIdx.y*128;
    Ent* st = stg + wid*SCAP;
    float4 dacc[NSEG];
#pragma unroll
    for (int s = 0; s < NSEG; s++) dacc[s] = make_float4(0.f,0.f,0.f,0.f);

    for (int p = 0; p < 4; p++) {
        __syncthreads();
        for (int idx = tid; idx < 256*32; idx += 512) {
            int r = idx >> 5, c = idx & 31;
            ((float4*)tile)[idx] = *(const float4*)&g_ctxT[(size_t)(256*p + r)*BB + b0 + c*4];
        }
        __syncthreads();
        // preload s=0
        int n = cnts[(u*NSEG + 0)*4 + p];
        const Ent* lp = g_segL[layer] + (size_t)(u*NSEG + 0)*SEG_STRIDE + p*SCAP;
        Ent c0 = {0,0}, c1 = {0,0};
        if (lane < n) c0 = lp[lane];
        if (lane < 16 && lane + 32 < n) c1 = lp[lane+32];
#pragma unroll
        for (int s = 0; s < NSEG; s++) {
            st[lane] = c0;
            if (lane < 16) st[lane+32] = c1;
            __syncwarp();
            int ncur = n;
            if (s < NSEG-1) {
                n = cnts[(u*NSEG + s+1)*4 + p];
                lp = g_segL[layer] + (size_t)(u*NSEG + s+1)*SEG_STRIDE + p*SCAP;
                c0 = {0,0}; c1 = {0,0};
                if (lane < n) c0 = lp[lane];
                if (lane < 16 && lane + 32 < n) c1 = lp[lane+32];
            }
            float4 a = dacc[s];
            for (int j = 0; j < ncur; j++) {
                Ent e = st[j];
                float4 cv = *(const float4*)((const char*)tile + e.off + lane*16);
                a.x += cv.x*e.v; a.y += cv.y*e.v; a.z += cv.z*e.v; a.w += cv.w*e.v;
            }
            dacc[s] = a;
            __syncwarp();
        }
    }
    // per-batch abs-argmax over segments (strict > = first-index tie rule)
    float4 best = make_float4(-1.f,-1.f,-1.f,-1.f);
    float4 ch   = make_float4(0.f,0.f,0.f,0.f);
#pragma unroll
    for (int s = 0; s < NSEG; s++) {
        float4 d = dacc[s];
        if (fabsf(d.x) > best.x) { best.x = fabsf(d.x); ch.x = d.x; }
        if (fabsf(d.y) > best.y) { best.y = fabsf(d.y); ch.y = d.y; }
        if (fabsf(d.z) > best.z) { best.z = fabsf(d.z); ch.z = d.z; }
        if (fabsf(d.w) > best.w) { best.w = fabsf(d.w); ch.w = d.w; }
    }
    float4 yf = *(const float4*)&g_yffT[(size_t)u*BB + b0 + lane*4];
    float4 o;
    o.x = yf.x / (1.f + __expf(-ch.x));
    o.y = yf.y / (1.f + __expf(-ch.y));
    o.z = yf.z / (1.f + __expf(-ch.z));
    o.w = yf.w / (1.f + __expf(-ch.w));
    *(float4*)&g_yT[(size_t)u*BB + b0 + lane*4] = o;
}

// ---------------- exact per-row top-K (radix select) ----------------
__global__ void kwin_kernel()
{
    __shared__ unsigned keys[HID];
    __shared__ float vals[HID];
    __shared__ int hist[256];
    __shared__ int s_digit, s_kk;
    __shared__ unsigned char keep[HID];
    int b = blockIdx.x, tid = threadIdx.x;   // 256 threads
    for (int r = 0; r < HID/256; r++) {
        int u = tid + r*256;
        float f = g_yT[(size_t)u*BB + b];
        vals[u] = f;
        unsigned x = __float_as_uint(f);
        keys[u] = (x & 0x80000000u) ? ~x : (x | 0x80000000u);
    }
    if (tid == 0) s_kk = KWIN;
    __syncthreads();
    unsigned pref = 0, pmask = 0;
    for (int pass = 0; pass < 4; pass++) {
        int shift = 24 - 8*pass;
        hist[tid] = 0;
        __syncthreads();
        for (int r = 0; r < HID/256; r++) {
            unsigned kk = keys[tid + r*256];
            if ((kk & pmask) == pref) atomicAdd(&hist[(kk >> shift) & 255], 1);
        }
        __syncthreads();
        if (tid == 0) {
            int kk = s_kk, d = 255;
            for (; d > 0; d--) { if (hist[d] >= kk) break; kk -= hist[d]; }
            s_digit = d; s_kk = kk;
        }
        __syncthreads();
        pref  |= ((unsigned)s_digit) << shift;
        pmask |= 0xFFu << shift;
    }
    unsigned kth = pref;
    int need_eq = s_kk;
    for (int r = 0; r < HID/256; r++) {
        int u = tid + r*256;
        unsigned kk = keys[u];
        bool kp = (kk > kth);
        if (kk == kth) {
            int cnt = 0;
            for (int j = 0; j < u; j++) if (keys[j] == kth) cnt++;
            kp = (cnt < need_eq);
        }
        keep[u] = kp;
        g_hT[(size_t)u*BB + b] = kp ? vals[u] : 0.f;
    }
    __syncthreads();
    if (tid < 32) {
        int base = 0;
        for (int ch = 0; ch < HID/32; ch++) {
            int u = ch*32 + tid;
            bool kp = keep[u] != 0;
            unsigned mm = __ballot_sync(0xFFFFFFFFu, kp);
            if (kp) {
                int pos = base + __popc(mm & ((1u << tid) - 1u));
                g_win[b*KWIN + pos].v = vals[u];
                g_win[b*KWIN + pos].off = (unsigned)u;
            }
            base += __popc(mm);
        }
    }
}

// ---------------- Dale output head on winner lists ----------------
__global__ void out_kernel(const float* __restrict__ Wex, const float* __restrict__ Wix,
                           const float* __restrict__ Wei, const float* __restrict__ bout,
                           float* __restrict__ out)
{
    __shared__ float sv[KWIN];
    __shared__ int   si[KWIN];
    __shared__ float red[128];
    int b = blockIdx.x, tid = threadIdx.x;   // 128 threads
    if (tid < KWIN) { Ent e = g_win[b*KWIN + tid]; sv[tid] = e.v; si[tid] = (int)e.off; }
    __syncthreads();
    float tpart = 0.f;
    for (int k = tid; k < KWIN; k += 128) tpart += sv[k]*Wix[si[k]];
    red[tid] = tpart;
    __syncthreads();
    for (int s = 64; s > 0; s >>= 1) { if (tid < s) red[tid] += red[tid+s]; __syncthreads(); }
    float t = red[0];
    if (tid < OUT_DIM) {
        float a = 0.f;
        const float* Wr = Wex + (size_t)tid*HID;
        for (int k = 0; k < KWIN; k++) a += sv[k]*Wr[si[k]];
        out[b*OUT_DIM + tid] = a - Wei[tid]*t + bout[tid];
    }
}

// ---------------- launch ----------------
extern "C" void kernel_launch(void* const* d_in, const int* in_sizes, int n_in,
                              void* d_out, int out_size)
{
    const float* x      = (const float*)d_in[0];
    const float* ctx    = (const float*)d_in[1];
    const float* W1     = (const float*)d_in[2];
    const float* b1     = (const float*)d_in[3];
    const float* segW1  = (const float*)d_in[4];
    const float* maskW1 = (const float*)d_in[5];
    const float* maskS1 = (const float*)d_in[6];
    const float* W2     = (const float*)d_in[7];
    const float* b2     = (const float*)d_in[8];
    const float* segW2  = (const float*)d_in[9];
    const float* maskW2 = (const float*)d_in[10];
    const float* maskS2 = (const float*)d_in[11];
    const float* Wex    = (const float*)d_in[12];
    const float* Wix    = (const float*)d_in[13];
    const float* Wei    = (const float*)d_in[14];
    const float* bout   = (const float*)d_in[15];
    float* out = (float*)d_out;

    const int FF_SMEM   = 1024*32*4 + 16*FCAP*8;   // 128K + 13.3K
    const int DEND_SMEM = 256*128*4 + 16*SCAP*8;   // 128K + 6K
    cudaFuncSetAttribute((const void*)ff_kernel,   cudaFuncAttributeMaxDynamicSharedMemorySize, FF_SMEM);
    cudaFuncSetAttribute((const void*)dend_kernel, cudaFuncAttributeMaxDynamicSharedMemorySize, DEND_SMEM);

    dim3 tb(32, 8);
    transpose_kernel<<<dim3(D_CTX/32, BB/32), tb>>>(ctx, D_CTX, 0);
    transpose_kernel<<<dim3(D_IN/32,  BB/32), tb>>>(x,   D_IN,  1);

    extract_seg_kernel<<<NROWS_SEG, 128>>>(segW1, maskS1, 0);
    extract_seg_kernel<<<NROWS_SEG, 128>>>(segW2, maskS2, 1);
    extract_ff_kernel <<<HID,       256>>>(W1, maskW1, 0);
    extract_ff_kernel <<<HID,       256>>>(W2, maskW2, 1);

    dim3 ffg(HID/64, BB/32);     // (32, 8)
    dim3 ddg(HID/16, BB/128);    // (128, 2)

    ff_kernel  <<<ffg, 512, FF_SMEM>>>(0, b1);
    dend_kernel<<<ddg, 512, DEND_SMEM>>>(0);
    kwin_kernel<<<BB, 256>>>();

    ff_kernel  <<<ffg, 512, FF_SMEM>>>(1, b2);
    dend_kernel<<<ddg, 512, DEND_SMEM>>>(1);
    kwin_kernel<<<BB, 256>>>();

    out_kernel<<<BB, 128>>>(Wex, Wix, Wei, bout, out);
}